// round 11
// baseline (speedup 1.0000x reference)
#include <cuda_runtime.h>
#include <cstdint>

#define N_NODES 100000
#define N_EDGES 1000000
#define D 64

// Scratch accumulator for scatter_add(messages); residual folded into GEMM.
__device__ float4 g_agg4[N_NODES * (D / 4)];
__device__ int g_ei_is64;

// ---------------------------------------------------------------------------
// Probe: edge_index int64 vs int32 (odd 32-bit words all zero => int64).
// ---------------------------------------------------------------------------
__global__ void probe_kernel(const unsigned int* __restrict__ ei_words) {
    int lane = threadIdx.x;
    unsigned int nz = 0;
#pragma unroll
    for (int r = 0; r < 4; r++) nz |= ei_words[2 * (lane + 32 * r) + 1];
    unsigned int any = __ballot_sync(0xFFFFFFFFu, nz != 0u);
    if (lane == 0) g_ei_is64 = (any == 0u) ? 1 : 0;
}

// ---------------------------------------------------------------------------
// Kernel 1: agg = 0 (write-only; residual folded into GEMM).
// ---------------------------------------------------------------------------
__global__ void init_kernel() {
    int i = blockIdx.x * blockDim.x + threadIdx.x;
    if (i < N_NODES * (D / 4)) g_agg4[i] = make_float4(0.f, 0.f, 0.f, 0.f);
}

// ---------------------------------------------------------------------------
// Kernel 2: edge scatter. 16 lanes per edge, one float4 per lane.
//   agg[dst][j] += feat[src][j] * w   via red.global.add.v4.f32.
// ---------------------------------------------------------------------------
__global__ void scatter_kernel(const float4* __restrict__ feat4,
                               const void* __restrict__ edge_index,
                               const float* __restrict__ edge_weight) {
    int gid = blockIdx.x * blockDim.x + threadIdx.x;
    int e = gid >> 4;
    int j = gid & 15;
    if (e >= N_EDGES) return;

    int src, dst;
    if (g_ei_is64) {
        const long long* ei = (const long long*)edge_index;
        src = (int)ei[e];
        dst = (int)ei[N_EDGES + e];
    } else {
        const int* ei = (const int*)edge_index;
        src = ei[e];
        dst = ei[N_EDGES + e];
    }
    if ((unsigned)src >= N_NODES || (unsigned)dst >= N_NODES) return;

    float w = edge_weight[e];
    float4 f = feat4[src * 16 + j];
    f.x *= w; f.y *= w; f.z *= w; f.w *= w;

    float4* p = g_agg4 + dst * 16 + j;
    asm volatile("red.global.add.v4.f32 [%0], {%1, %2, %3, %4};"
                 :: "l"(p), "f"(f.x), "f"(f.y), "f"(f.z), "f"(f.w)
                 : "memory");
}

// ---------------------------------------------------------------------------
// Kernel 3: out = (agg + feat) @ W^T + b.
// grid = (782, 2): blockIdx.x = 128-node tile, blockIdx.y = 32-output half.
// Thread (mt, nt): 8 nodes (4 f32x2 pairs along m) x 4 outputs -> 32 acc regs.
//
// x tile staged TRANSPOSED (xs[k][m]) in two K-halves (16 KB).
// This block's 32 W-columns staged k-major DUPLICATED:
//   ws2[k][2n] = ws2[k][2n+1] = W[(ny*32+n)*64 + k]   (16 KB)
// so one LDS.128 yields {w,w,w',w'} = two f32x2 operands, zero packing movs.
// Inner loop per k: 2 LDS.128 (x) + 2 LDS.128 (w) + 16 fma.rn.f32x2.
// ---------------------------------------------------------------------------
__global__ void __launch_bounds__(128, 6) gemm_kernel(const float4* __restrict__ feat4,
                                                      const float* __restrict__ W,
                                                      const float* __restrict__ bias,
                                                      float* __restrict__ out) {
    __shared__ float xs[32][128];   // 16 KB: xs[k - half*32][m]
    __shared__ float ws2[64][64];   // 16 KB: ws2[k][2n{+0,1}] dup'd

    const int tid = threadIdx.x;
    const int nt = tid >> 4;        // 0..7  -> outputs ny*32 + nt*4 .. +3
    const int mt = tid & 15;        // 0..15 -> nodes   mt*8 .. mt*8+7
    const int ny = blockIdx.y;      // 0..1  -> output half
    const int base = blockIdx.x * 128;
    const int obase = ny * 32;

    // Stage ws2: 2048 (k, n) entries, 16 per thread, dup'd as float2.
    for (int idx = tid; idx < 2048; idx += 128) {
        int k = idx >> 5;
        int n = idx & 31;
        float w = W[(obase + n) * 64 + k];
        *(float2*)&ws2[k][2 * n] = make_float2(w, w);
    }

    // Init accumulators with bias (replicated into both f32x2 lanes).
    unsigned long long acc[4][4];   // [out j][m-pair i]
#pragma unroll
    for (int j = 0; j < 4; j++) {
        float bj = __ldg(&bias[obase + nt * 4 + j]);
        unsigned long long bp;
        asm("mov.b64 %0, {%1, %1};" : "=l"(bp) : "f"(bj));
#pragma unroll
        for (int i = 0; i < 4; i++) acc[j][i] = bp;
    }

    const int my_node = base + tid;
    const bool valid = my_node < N_NODES;

#pragma unroll
    for (int h = 0; h < 2; h++) {
        if (h) __syncthreads();   // protect xs before overwrite
        // Stage this K-half of x = agg + feat, transposed. Zero-fill tail.
#pragma unroll
        for (int c = 0; c < 8; c++) {
            float4 v = make_float4(0.f, 0.f, 0.f, 0.f);
            if (valid) {
                float4 a = g_agg4[my_node * 16 + h * 8 + c];
                float4 f = feat4[my_node * 16 + h * 8 + c];
                v = make_float4(a.x + f.x, a.y + f.y, a.z + f.z, a.w + f.w);
            }
            xs[c * 4 + 0][tid] = v.x;
            xs[c * 4 + 1][tid] = v.y;
            xs[c * 4 + 2][tid] = v.z;
            xs[c * 4 + 3][tid] = v.w;
        }
        __syncthreads();

#pragma unroll 8
        for (int kk = 0; kk < 32; kk++) {
            const int k = h * 32 + kk;
            // x: 4 f32x2 pairs along the node dimension (natural pairs)
            ulonglong2 xa = *(const ulonglong2*)&xs[kk][mt * 8];
            ulonglong2 xb = *(const ulonglong2*)&xs[kk][mt * 8 + 4];
            unsigned long long xp0 = xa.x, xp1 = xa.y, xp2 = xb.x, xp3 = xb.y;
            // w: 2 LDS.128 = 4 replicated f32x2 operands, no movs
            ulonglong2 wa = *(const ulonglong2*)&ws2[k][nt * 8];
            ulonglong2 wb = *(const ulonglong2*)&ws2[k][nt * 8 + 4];
            unsigned long long w0 = wa.x, w1 = wa.y, w2 = wb.x, w3 = wb.y;

            asm("fma.rn.f32x2 %0, %1, %2, %0;" : "+l"(acc[0][0]) : "l"(xp0), "l"(w0));
            asm("fma.rn.f32x2 %0, %1, %2, %0;" : "+l"(acc[0][1]) : "l"(xp1), "l"(w0));
            asm("fma.rn.f32x2 %0, %1, %2, %0;" : "+l"(acc[0][2]) : "l"(xp2), "l"(w0));
            asm("fma.rn.f32x2 %0, %1, %2, %0;" : "+l"(acc[0][3]) : "l"(xp3), "l"(w0));
            asm("fma.rn.f32x2 %0, %1, %2, %0;" : "+l"(acc[1][0]) : "l"(xp0), "l"(w1));
            asm("fma.rn.f32x2 %0, %1, %2, %0;" : "+l"(acc[1][1]) : "l"(xp1), "l"(w1));
            asm("fma.rn.f32x2 %0, %1, %2, %0;" : "+l"(acc[1][2]) : "l"(xp2), "l"(w1));
            asm("fma.rn.f32x2 %0, %1, %2, %0;" : "+l"(acc[1][3]) : "l"(xp3), "l"(w1));
            asm("fma.rn.f32x2 %0, %1, %2, %0;" : "+l"(acc[2][0]) : "l"(xp0), "l"(w2));
            asm("fma.rn.f32x2 %0, %1, %2, %0;" : "+l"(acc[2][1]) : "l"(xp1), "l"(w2));
            asm("fma.rn.f32x2 %0, %1, %2, %0;" : "+l"(acc[2][2]) : "l"(xp2), "l"(w2));
            asm("fma.rn.f32x2 %0, %1, %2, %0;" : "+l"(acc[2][3]) : "l"(xp3), "l"(w2));
            asm("fma.rn.f32x2 %0, %1, %2, %0;" : "+l"(acc[3][0]) : "l"(xp0), "l"(w3));
            asm("fma.rn.f32x2 %0, %1, %2, %0;" : "+l"(acc[3][1]) : "l"(xp1), "l"(w3));
            asm("fma.rn.f32x2 %0, %1, %2, %0;" : "+l"(acc[3][2]) : "l"(xp2), "l"(w3));
            asm("fma.rn.f32x2 %0, %1, %2, %0;" : "+l"(acc[3][3]) : "l"(xp3), "l"(w3));
        }
    }

    // Epilogue: per m-pair, each thread stores a float4 (4 consecutive outs)
    // for each of the two nodes in the pair.
#pragma unroll
    for (int i = 0; i < 4; i++) {
        int m0 = base + mt * 8 + 2 * i;
        float2 a0 = *(float2*)&acc[0][i];
        float2 a1 = *(float2*)&acc[1][i];
        float2 a2 = *(float2*)&acc[2][i];
        float2 a3 = *(float2*)&acc[3][i];
        if (m0 < N_NODES) {
            *(float4*)(out + (size_t)m0 * D + obase + nt * 4) =
                make_float4(a0.x, a1.x, a2.x, a3.x);
        }
        if (m0 + 1 < N_NODES) {
            *(float4*)(out + (size_t)(m0 + 1) * D + obase + nt * 4) =
                make_float4(a0.y, a1.y, a2.y, a3.y);
        }
    }
}

// ---------------------------------------------------------------------------
extern "C" void kernel_launch(void* const* d_in, const int* in_sizes, int n_in,
                              void* d_out, int out_size) {
    // Resolve inputs by element count (robust to metadata ordering).
    const float* feat = nullptr;
    const void*  ei   = nullptr;
    const float* ew   = nullptr;
    const float* W    = nullptr;
    const float* b    = nullptr;

    for (int i = 0; i < n_in; i++) {
        switch (in_sizes[i]) {
            case 6400000: feat = (const float*)d_in[i]; break;
            case 2000000: ei   = d_in[i];               break;
            case 1000000: ew   = (const float*)d_in[i]; break;
            case 4096:    W    = (const float*)d_in[i]; break;
            case 64:      b    = (const float*)d_in[i]; break;
        }
    }
    float* out = (float*)d_out;
    (void)out_size;

    probe_kernel<<<1, 32>>>((const unsigned int*)ei);

    const int init_total = N_NODES * (D / 4);
    init_kernel<<<(init_total + 255) / 256, 256>>>();

    const int scatter_lanes = N_EDGES * 16;
    scatter_kernel<<<(scatter_lanes + 255) / 256, 256>>>((const float4*)feat, ei, ew);

    dim3 ggrid((N_NODES + 127) / 128, 2);
    gemm_kernel<<<ggrid, 128>>>((const float4*)feat, W, b, out);
}